// round 1
// baseline (speedup 1.0000x reference)
#include <cuda_runtime.h>

// SpectralInverse: out[b,p,o] = u_b[o] + sum_m u_w[o,m] * sin( (sum_f h[b,f,m]*cos(2pi*(y_w[f].pos + y_b[f]))) / Ngrid )
// Shapes: B=4, F=128, Cin=64, Cout=8, grid 48^3 per batch.

#define BATCH 4
#define NF 128
#define CIN 64
#define COUT 8
#define NGRID (48*48*48)          // 110592
#define TPB 256
#define BLKS_PER_BATCH (NGRID / TPB)  // 432

__device__ __forceinline__ unsigned long long ffma2(unsigned long long a,
                                                    unsigned long long b,
                                                    unsigned long long c) {
    unsigned long long d;
    asm("fma.rn.f32x2 %0, %1, %2, %3;" : "=l"(d) : "l"(a), "l"(b), "l"(c));
    return d;
}
__device__ __forceinline__ unsigned long long pack2(float x, float y) {
    unsigned long long d;
    asm("mov.b64 %0, {%1, %2};" : "=l"(d) : "f"(x), "f"(y));
    return d;
}
__device__ __forceinline__ void unpack2(unsigned long long v, float& x, float& y) {
    asm("mov.b64 {%0, %1}, %2;" : "=f"(x), "=f"(y) : "l"(v));
}

__global__ void __launch_bounds__(TPB)
spectral_inverse_kernel(const float* __restrict__ h,
                        const float* __restrict__ y,
                        const float* __restrict__ y_w,
                        const float* __restrict__ y_b,
                        const float* __restrict__ u_w,
                        const float* __restrict__ u_b,
                        float* __restrict__ out)
{
    // h[b] rows: 128 x 64 floats = 32KB, stored as float4 for LDS.128 broadcast reads
    __shared__ float4 s_h[NF * (CIN / 4)];
    __shared__ float4 s_yw[NF];           // (w0, w1, w2, bias)
    __shared__ float  s_uw[COUT * CIN];
    __shared__ float  s_ub[COUT];

    const int tid = threadIdx.x;
    const int b   = blockIdx.x / BLKS_PER_BATCH;
    const int blk = blockIdx.x % BLKS_PER_BATCH;
    const int p   = blk * TPB + tid;      // point index within batch

    // ---- stage weights into shared ----
    const float4* hb = (const float4*)(h + (size_t)b * NF * CIN);
    #pragma unroll 2
    for (int i = tid; i < NF * (CIN / 4); i += TPB) s_h[i] = hb[i];
    for (int i = tid; i < NF; i += TPB)
        s_yw[i] = make_float4(y_w[i * 3 + 0], y_w[i * 3 + 1], y_w[i * 3 + 2], y_b[i]);
    for (int i = tid; i < COUT * CIN; i += TPB) s_uw[i] = u_w[i];
    if (tid < COUT) s_ub[tid] = u_b[tid];
    __syncthreads();

    // ---- this thread's grid position ----
    const float* yp = y + ((size_t)b * NGRID + p) * 3;
    const float p0 = yp[0], p1 = yp[1], p2 = yp[2];

    // ---- packed f32x2 accumulators for U[0..63] ----
    unsigned long long acc[CIN / 2];
    #pragma unroll
    for (int i = 0; i < CIN / 2; i++) acc[i] = 0ull;

    #pragma unroll 4
    for (int f = 0; f < NF; f++) {
        float4 w = s_yw[f];
        float t = fmaf(w.x, p0, fmaf(w.y, p1, fmaf(w.z, p2, w.w)));
        // cos(2*pi*t): exact period reduction (t - rint(t) is exact), then fast cos on [-pi, pi]
        float r = t - rintf(t);
        float c = __cosf(6.2831853071795864f * r);
        unsigned long long cc = pack2(c, c);

        const float4* hf = &s_h[f * (CIN / 4)];
        #pragma unroll
        for (int q = 0; q < CIN / 4; q++) {
            float4 v = hf[q];
            acc[2 * q]     = ffma2(pack2(v.x, v.y), cc, acc[2 * q]);
            acc[2 * q + 1] = ffma2(pack2(v.z, v.w), cc, acc[2 * q + 1]);
        }
    }

    // ---- activation: sin(U / n_grid) ----
    const float inv_n = 1.0f / (float)NGRID;
    float su[CIN];
    #pragma unroll
    for (int q = 0; q < CIN / 2; q++) {
        float a0, a1;
        unpack2(acc[q], a0, a1);
        su[2 * q]     = sinf(a0 * inv_n);
        su[2 * q + 1] = sinf(a1 * inv_n);
    }

    // ---- output projection: 8 outputs ----
    float o[COUT];
    #pragma unroll
    for (int oo = 0; oo < COUT; oo++) {
        float s = s_ub[oo];
        #pragma unroll
        for (int m = 0; m < CIN; m++)
            s = fmaf(s_uw[oo * CIN + m], su[m], s);
        o[oo] = s;
    }

    float4* op = (float4*)(out + ((size_t)b * NGRID + p) * COUT);
    op[0] = make_float4(o[0], o[1], o[2], o[3]);
    op[1] = make_float4(o[4], o[5], o[6], o[7]);
}

extern "C" void kernel_launch(void* const* d_in, const int* in_sizes, int n_in,
                              void* d_out, int out_size) {
    const float* h   = (const float*)d_in[0];
    const float* y   = (const float*)d_in[1];
    const float* y_w = (const float*)d_in[2];
    const float* y_b = (const float*)d_in[3];
    const float* u_w = (const float*)d_in[4];
    const float* u_b = (const float*)d_in[5];
    float* out = (float*)d_out;

    dim3 grid(BATCH * BLKS_PER_BATCH);   // 1728 blocks
    spectral_inverse_kernel<<<grid, TPB>>>(h, y, y_w, y_b, u_w, u_b, out);
}

// round 3
// speedup vs baseline: 4.5208x; 4.5208x over previous
#include <cuda_runtime.h>
#include <cuda_bf16.h>
#include <cstdint>

// SpectralInverse via warp-level bf16 HMMA (mma.sync m16n8k16), fp32 accum.
// U = C * (h_hi + h_lo)  [h split into two bf16 tiles; C = cos(2pi*Y) single bf16]
// out = u_b + (u_w/Ngrid) * U   [sin(x)~x exact to 2e-9 rel at |x|<4e-4], as a second MMA.

#define BATCH 4
#define NF 128
#define CIN 64
#define COUT 8
#define NGRID (48*48*48)
#define TPB 512
#define PTS_PER_CTA 256
#define CTAS_PER_BATCH (NGRID / PTS_PER_CTA)   // 432
#define TWO_PI_F 6.28318530717958647692f

// B tile: k-pair packed bf16 words, row j' = f/2 in [0,64), padded row stride 72 words
#define BSTRIDE 72

__device__ __forceinline__ uint32_t pack_bf16x2(float lo, float hi) {
    uint32_t r;
    asm("cvt.rn.bf16x2.f32 %0, %1, %2;" : "=r"(r) : "f"(hi), "f"(lo));
    return r;  // r[15:0] = bf16(lo), r[31:16] = bf16(hi)
}

__device__ __forceinline__ void mma16816(float& d0, float& d1, float& d2, float& d3,
                                          uint32_t a0, uint32_t a1, uint32_t a2, uint32_t a3,
                                          uint32_t b0, uint32_t b1) {
    asm volatile("mma.sync.aligned.m16n8k16.row.col.f32.bf16.bf16.f32 "
                 "{%0,%1,%2,%3}, {%4,%5,%6,%7}, {%8,%9}, {%0,%1,%2,%3};"
                 : "+f"(d0), "+f"(d1), "+f"(d2), "+f"(d3)
                 : "r"(a0), "r"(a1), "r"(a2), "r"(a3), "r"(b0), "r"(b1));
}

__device__ __forceinline__ float cosv(float4 w, float4 p) {
    float t = fmaf(w.x, p.x, fmaf(w.y, p.y, fmaf(w.z, p.z, w.w)));
    float r = t - rintf(t);          // exact period reduction to [-0.5, 0.5] turns
    return __cosf(TWO_PI_F * r);
}

__global__ void __launch_bounds__(TPB, 1)
spectral_hmma_kernel(const float* __restrict__ h,
                     const float* __restrict__ y,
                     const float* __restrict__ y_w,
                     const float* __restrict__ y_b,
                     const float* __restrict__ u_w,
                     const float* __restrict__ u_b,
                     float* __restrict__ out)
{
    __shared__ uint32_t s_bhi[64 * BSTRIDE];   // 18432 B
    __shared__ uint32_t s_blo[64 * BSTRIDE];   // 18432 B
    __shared__ float4   s_pts[PTS_PER_CTA];    // 4096 B
    __shared__ float4   s_yw[NF];              // 2048 B
    __shared__ uint32_t s_uwp[COUT * 40];      // 1280 B  (u_w/N as bf16 pairs, stride 40)
    __shared__ float    s_ub[COUT];

    const int tid  = threadIdx.x;
    const int bIdx = blockIdx.x / CTAS_PER_BATCH;
    const int blk  = blockIdx.x % CTAS_PER_BATCH;

    // ---------------- staging ----------------
    {   // h -> bf16 hi/lo split, k-pair packed: word[f/2][m], halves = (f&1)
        const float* hb = h + (size_t)bIdx * NF * CIN;
        __nv_bfloat16* bh = (__nv_bfloat16*)s_bhi;
        __nv_bfloat16* bl = (__nv_bfloat16*)s_blo;
        #pragma unroll
        for (int it = 0; it < (NF * CIN) / TPB; it++) {
            int i = tid + it * TPB;
            int f = i >> 6, m = i & 63;
            float v = hb[i];
            __nv_bfloat16 hi = __float2bfloat16(v);
            float lo = v - __bfloat162float(hi);
            int idx = ((f >> 1) * BSTRIDE + m) * 2 + (f & 1);
            bh[idx] = hi;
            bl[idx] = __float2bfloat16(lo);
        }
    }
    if (tid < NF)
        s_yw[tid] = make_float4(y_w[tid * 3], y_w[tid * 3 + 1], y_w[tid * 3 + 2], y_b[tid]);
    {   // grid positions, padded to float4
        const float* yg = y + ((size_t)bIdx * NGRID + (size_t)blk * PTS_PER_CTA) * 3;
        float* sp = (float*)s_pts;
        #pragma unroll
        for (int it = 0; it < (PTS_PER_CTA * 4) / TPB; it++) {
            int j = tid + it * TPB;
            int pt = j >> 2, c = j & 3;
            sp[j] = (c < 3) ? yg[pt * 3 + c] : 0.0f;
        }
    }
    if (tid < (COUT * CIN) / 2) {   // u_w * (1/NGRID) as bf16 pairs along m
        int o = tid >> 5, j = tid & 31;
        const float inv_n = 1.0f / (float)NGRID;
        s_uwp[o * 40 + j] = pack_bf16x2(u_w[o * CIN + 2 * j] * inv_n,
                                        u_w[o * CIN + 2 * j + 1] * inv_n);
    }
    if (tid < COUT) s_ub[tid] = u_b[tid];
    __syncthreads();

    // ---------------- main: per-warp 16 rows x 64 cols ----------------
    const int warp = tid >> 5;
    const int lane = tid & 31;
    const int g  = lane >> 2;       // row group 0..7
    const int i4 = lane & 3;        // col/quad index 0..3
    const int rA = warp * 16 + g;   // row within CTA
    const float4 pA = s_pts[rA];
    const float4 pB = s_pts[rA + 8];

    float acc[8][4];
    #pragma unroll
    for (int nt = 0; nt < 8; nt++) {
        acc[nt][0] = 0.f; acc[nt][1] = 0.f; acc[nt][2] = 0.f; acc[nt][3] = 0.f;
    }

    const uint32_t* bh0 = s_bhi + i4 * BSTRIDE + g;
    const uint32_t* bl0 = s_blo + i4 * BSTRIDE + g;

    #pragma unroll
    for (int kt = 0; kt < 8; kt++) {
        const int c0 = kt * 16 + 2 * i4;
        float4 w0 = s_yw[c0], w1 = s_yw[c0 + 1], w2 = s_yw[c0 + 8], w3 = s_yw[c0 + 9];
        // A fragment: cos values computed straight into mma layout
        uint32_t a0 = pack_bf16x2(cosv(w0, pA), cosv(w1, pA));
        uint32_t a1 = pack_bf16x2(cosv(w0, pB), cosv(w1, pB));
        uint32_t a2 = pack_bf16x2(cosv(w2, pA), cosv(w3, pA));
        uint32_t a3 = pack_bf16x2(cosv(w2, pB), cosv(w3, pB));

        const uint32_t* bh = bh0 + kt * (8 * BSTRIDE);
        const uint32_t* bl = bl0 + kt * (8 * BSTRIDE);
        #pragma unroll
        for (int nt = 0; nt < 8; nt++) {
            mma16816(acc[nt][0], acc[nt][1], acc[nt][2], acc[nt][3],
                     a0, a1, a2, a3, bh[nt * 8], bh[nt * 8 + 4 * BSTRIDE]);
            mma16816(acc[nt][0], acc[nt][1], acc[nt][2], acc[nt][3],
                     a0, a1, a2, a3, bl[nt * 8], bl[nt * 8 + 4 * BSTRIDE]);
        }
    }

    // ---------------- epilogue: out = u_b + (u_w/N) * U  (one more MMA) ----------------
    float e0 = s_ub[2 * i4], e1 = s_ub[2 * i4 + 1];
    float e2 = e0, e3 = e1;
    #pragma unroll
    for (int kt2 = 0; kt2 < 4; kt2++) {
        uint32_t a0 = pack_bf16x2(acc[2 * kt2][0],     acc[2 * kt2][1]);
        uint32_t a1 = pack_bf16x2(acc[2 * kt2][2],     acc[2 * kt2][3]);
        uint32_t a2 = pack_bf16x2(acc[2 * kt2 + 1][0], acc[2 * kt2 + 1][1]);
        uint32_t a3 = pack_bf16x2(acc[2 * kt2 + 1][2], acc[2 * kt2 + 1][3]);
        uint32_t b0 = s_uwp[g * 40 + 8 * kt2 + i4];
        uint32_t b1 = s_uwp[g * 40 + 8 * kt2 + i4 + 4];
        mma16816(e0, e1, e2, e3, a0, a1, a2, a3, b0, b1);
    }

    const size_t ptA = (size_t)bIdx * NGRID + (size_t)blk * PTS_PER_CTA + rA;
    float2* oA = (float2*)(out + ptA * COUT + 2 * i4);
    float2* oB = (float2*)(out + (ptA + 8) * COUT + 2 * i4);
    *oA = make_float2(e0, e1);
    *oB = make_float2(e2, e3);
}

extern "C" void kernel_launch(void* const* d_in, const int* in_sizes, int n_in,
                              void* d_out, int out_size) {
    const float* h   = (const float*)d_in[0];
    const float* y   = (const float*)d_in[1];
    const float* y_w = (const float*)d_in[2];
    const float* y_b = (const float*)d_in[3];
    const float* u_w = (const float*)d_in[4];
    const float* u_b = (const float*)d_in[5];
    float* out = (float*)d_out;

    dim3 grid(BATCH * CTAS_PER_BATCH);   // 1728 CTAs
    spectral_hmma_kernel<<<grid, TPB>>>(h, y, y_w, y_b, u_w, u_b, out);
}

// round 4
// speedup vs baseline: 8.1931x; 1.8123x over previous
#include <cuda_runtime.h>
#include <cuda_bf16.h>
#include <cstdint>

// SpectralInverse via warp-level bf16 HMMA (mma.sync m16n8k16), fp32 accum.
// U = C * h_hi (single bf16 h; cos single bf16), out = u_b + (u_w/Ngrid)*U as 2nd MMA.
// 2*pi folded into y_w/y_b at staging; __cosf handles period reduction internally.
// M=32 per warp: two A-fragment sets share each B (h) shared-memory load.

#define BATCH 4
#define NF 128
#define CIN 64
#define COUT 8
#define NGRID (48*48*48)
#define TPB 512
#define PTS_PER_CTA 512
#define CTAS_PER_BATCH (NGRID / PTS_PER_CTA)   // 216
#define TWO_PI_F 6.28318530717958647692f

// B tile: k-pair packed bf16 words, row j' = f/2 in [0,64), padded row stride 72 words
#define BSTRIDE 72

__device__ __forceinline__ uint32_t pack_bf16x2(float lo, float hi) {
    uint32_t r;
    asm("cvt.rn.bf16x2.f32 %0, %1, %2;" : "=r"(r) : "f"(hi), "f"(lo));
    return r;  // r[15:0]=bf16(lo), r[31:16]=bf16(hi)
}

__device__ __forceinline__ void mma16816(float* d,
                                          uint32_t a0, uint32_t a1, uint32_t a2, uint32_t a3,
                                          uint32_t b0, uint32_t b1) {
    asm volatile("mma.sync.aligned.m16n8k16.row.col.f32.bf16.bf16.f32 "
                 "{%0,%1,%2,%3}, {%4,%5,%6,%7}, {%8,%9}, {%0,%1,%2,%3};"
                 : "+f"(d[0]), "+f"(d[1]), "+f"(d[2]), "+f"(d[3])
                 : "r"(a0), "r"(a1), "r"(a2), "r"(a3), "r"(b0), "r"(b1));
}

// w is pre-scaled by 2*pi; __cosf's internal 1/(2pi) pre-scale + MUFU handles reduction.
__device__ __forceinline__ float cosv(float4 w, float3 p) {
    return __cosf(fmaf(w.x, p.x, fmaf(w.y, p.y, fmaf(w.z, p.z, w.w))));
}

__global__ void __launch_bounds__(TPB, 1)
spectral_hmma2_kernel(const float* __restrict__ h,
                      const float* __restrict__ y,
                      const float* __restrict__ y_w,
                      const float* __restrict__ y_b,
                      const float* __restrict__ u_w,
                      const float* __restrict__ u_b,
                      float* __restrict__ out)
{
    __shared__ uint32_t s_bhi[64 * BSTRIDE];   // 18432 B (h as bf16, k-pair packed)
    __shared__ float4   s_pts[PTS_PER_CTA];    // 8192 B
    __shared__ float4   s_yw[NF];              // 2048 B  (2pi * (w0,w1,w2,b))
    __shared__ uint32_t s_uwp[COUT * 40];      // 1280 B  (u_w/N bf16 pairs, stride 40)
    __shared__ float    s_ub[COUT];

    const int tid  = threadIdx.x;
    const int bIdx = blockIdx.x / CTAS_PER_BATCH;
    const int blk  = blockIdx.x % CTAS_PER_BATCH;

    // ---------------- staging ----------------
    {   // h -> bf16, k-pair packed: word[f/2][m], halves = (f&1)
        const float* hb = h + (size_t)bIdx * NF * CIN;
        __nv_bfloat16* bh = (__nv_bfloat16*)s_bhi;
        #pragma unroll
        for (int it = 0; it < (NF * CIN) / TPB; it++) {
            int i = tid + it * TPB;
            int f = i >> 6, m = i & 63;
            bh[((f >> 1) * BSTRIDE + m) * 2 + (f & 1)] = __float2bfloat16(hb[i]);
        }
    }
    if (tid < NF)
        s_yw[tid] = make_float4(TWO_PI_F * y_w[tid * 3],
                                TWO_PI_F * y_w[tid * 3 + 1],
                                TWO_PI_F * y_w[tid * 3 + 2],
                                TWO_PI_F * y_b[tid]);
    {   // grid positions, padded to float4
        const float* yg = y + ((size_t)bIdx * NGRID + (size_t)blk * PTS_PER_CTA) * 3;
        float* sp = (float*)s_pts;
        #pragma unroll
        for (int it = 0; it < (PTS_PER_CTA * 4) / TPB; it++) {
            int j = tid + it * TPB;
            int pt = j >> 2, c = j & 3;
            sp[j] = (c < 3) ? yg[pt * 3 + c] : 0.0f;
        }
    }
    if (tid < (COUT * CIN) / 2) {   // u_w * (1/NGRID) as bf16 pairs along m
        int o = tid >> 5, j = tid & 31;
        const float inv_n = 1.0f / (float)NGRID;
        s_uwp[o * 40 + j] = pack_bf16x2(u_w[o * CIN + 2 * j] * inv_n,
                                        u_w[o * CIN + 2 * j + 1] * inv_n);
    }
    if (tid < COUT) s_ub[tid] = u_b[tid];
    __syncthreads();

    // ---------------- main: per-warp 32 rows x 64 cols ----------------
    const int warp = tid >> 5;
    const int lane = tid & 31;
    const int g  = lane >> 2;        // row group 0..7
    const int i4 = lane & 3;         // quad index 0..3
    const int base = warp * 32;

    float4 q0 = s_pts[base + g];
    float4 q1 = s_pts[base + g + 8];
    float4 q2 = s_pts[base + g + 16];
    float4 q3 = s_pts[base + g + 24];
    const float3 p0 = make_float3(q0.x, q0.y, q0.z);
    const float3 p1 = make_float3(q1.x, q1.y, q1.z);
    const float3 p2 = make_float3(q2.x, q2.y, q2.z);
    const float3 p3 = make_float3(q3.x, q3.y, q3.z);

    float acc0[8][4], acc1[8][4];
    #pragma unroll
    for (int nt = 0; nt < 8; nt++)
        #pragma unroll
        for (int j = 0; j < 4; j++) { acc0[nt][j] = 0.f; acc1[nt][j] = 0.f; }

    const uint32_t* bh0 = s_bhi + i4 * BSTRIDE + g;

    #pragma unroll
    for (int kt = 0; kt < 8; kt++) {
        const int c0 = kt * 16 + 2 * i4;
        float4 w0 = s_yw[c0], w1 = s_yw[c0 + 1], w2 = s_yw[c0 + 8], w3 = s_yw[c0 + 9];
        // A fragments for both M-tiles, cos computed straight into mma layout
        uint32_t a0 = pack_bf16x2(cosv(w0, p0), cosv(w1, p0));
        uint32_t a1 = pack_bf16x2(cosv(w0, p1), cosv(w1, p1));
        uint32_t a2 = pack_bf16x2(cosv(w2, p0), cosv(w3, p0));
        uint32_t a3 = pack_bf16x2(cosv(w2, p1), cosv(w3, p1));
        uint32_t a4 = pack_bf16x2(cosv(w0, p2), cosv(w1, p2));
        uint32_t a5 = pack_bf16x2(cosv(w0, p3), cosv(w1, p3));
        uint32_t a6 = pack_bf16x2(cosv(w2, p2), cosv(w3, p2));
        uint32_t a7 = pack_bf16x2(cosv(w2, p3), cosv(w3, p3));

        const uint32_t* bh = bh0 + kt * (8 * BSTRIDE);
        #pragma unroll
        for (int nt = 0; nt < 8; nt++) {
            uint32_t b0 = bh[nt * 8];
            uint32_t b1 = bh[nt * 8 + 4 * BSTRIDE];
            mma16816(acc0[nt], a0, a1, a2, a3, b0, b1);   // rows base .. base+15
            mma16816(acc1[nt], a4, a5, a6, a7, b0, b1);   // rows base+16 .. base+31
        }
    }

    // ---------------- epilogue: out = u_b + (u_w/N) * U  (second MMA) ----------------
    const float ub0 = s_ub[2 * i4], ub1 = s_ub[2 * i4 + 1];
    float e0[4] = {ub0, ub1, ub0, ub1};
    float e1[4] = {ub0, ub1, ub0, ub1};
    #pragma unroll
    for (int kt2 = 0; kt2 < 4; kt2++) {
        uint32_t b0 = s_uwp[g * 40 + 8 * kt2 + i4];
        uint32_t b1 = s_uwp[g * 40 + 8 * kt2 + i4 + 4];
        mma16816(e0,
                 pack_bf16x2(acc0[2 * kt2][0],     acc0[2 * kt2][1]),
                 pack_bf16x2(acc0[2 * kt2][2],     acc0[2 * kt2][3]),
                 pack_bf16x2(acc0[2 * kt2 + 1][0], acc0[2 * kt2 + 1][1]),
                 pack_bf16x2(acc0[2 * kt2 + 1][2], acc0[2 * kt2 + 1][3]),
                 b0, b1);
        mma16816(e1,
                 pack_bf16x2(acc1[2 * kt2][0],     acc1[2 * kt2][1]),
                 pack_bf16x2(acc1[2 * kt2][2],     acc1[2 * kt2][3]),
                 pack_bf16x2(acc1[2 * kt2 + 1][0], acc1[2 * kt2 + 1][1]),
                 pack_bf16x2(acc1[2 * kt2 + 1][2], acc1[2 * kt2 + 1][3]),
                 b0, b1);
    }

    const size_t pt = (size_t)bIdx * NGRID + (size_t)blk * PTS_PER_CTA + base + g;
    *(float2*)(out + (pt +  0) * COUT + 2 * i4) = make_float2(e0[0], e0[1]);
    *(float2*)(out + (pt +  8) * COUT + 2 * i4) = make_float2(e0[2], e0[3]);
    *(float2*)(out + (pt + 16) * COUT + 2 * i4) = make_float2(e1[0], e1[1]);
    *(float2*)(out + (pt + 24) * COUT + 2 * i4) = make_float2(e1[2], e1[3]);
}

extern "C" void kernel_launch(void* const* d_in, const int* in_sizes, int n_in,
                              void* d_out, int out_size) {
    const float* h   = (const float*)d_in[0];
    const float* y   = (const float*)d_in[1];
    const float* y_w = (const float*)d_in[2];
    const float* y_b = (const float*)d_in[3];
    const float* u_w = (const float*)d_in[4];
    const float* u_b = (const float*)d_in[5];
    float* out = (float*)d_out;

    dim3 grid(BATCH * CTAS_PER_BATCH);   // 864 CTAs
    spectral_hmma2_kernel<<<grid, TPB>>>(h, y, y_w, y_b, u_w, u_b, out);
}